// round 10
// baseline (speedup 1.0000x reference)
#include <cuda_runtime.h>

// Problem shape (fixed by reference): B=64, M=64, P=128, V=32.
// Output = 0.5 * min over (m,p) of point-polygon distance, BATCH 63 ONLY.
#define BN 64
#define MN 64
#define PN 128
#define VN 32
#define EPSF 1e-12f

// ── Kernel 1: seed d_out with +inf bits (overwrites the 0xAA poison).
__global__ void pl_init(unsigned* __restrict__ out_bits) {
    out_bits[0] = 0x7F800000u;   // +inf
}

// ── Kernel 2 (PDL): full compute; atomicMin of final scalar candidates
//    straight into d_out. Nothing runs after this kernel.
__global__ void __launch_bounds__(MN)
pl_main(const float* __restrict__ last_point,
        const float* __restrict__ polygon_coords,
        unsigned* __restrict__ out_bits) {
    // WARP-PRIVATE edge tables: no __syncthreads, warps fully decoupled.
    // [warp][v]: e0 = { ax, ay, abx, aby }, e1 = { inv2, invdy, by, - }
    __shared__ float4 s_e0[2][VN];
    __shared__ float4 s_e1[2][VN];

    const int p = blockIdx.x;
    const int t = threadIdx.x;
    const int w = t >> 5;        // warp id (0/1)
    const int v = t & 31;        // lane == edge index

    // This thread's query point: last_point[63, t, :].
    const float2 pt = reinterpret_cast<const float2*>(last_point)[(BN - 1) * MN + t];
    const float px = pt.x;
    const float py = pt.y;

    // Polygon p of batch 63. Lane v loads ONLY vertex v; vertex v+1 comes from
    // a shuffle — one global-memory round instead of two.
    const float2* pc = reinterpret_cast<const float2*>(polygon_coords)
                       + (((BN - 1) * PN + p) * VN);
    {
        const float2 a = pc[v];
        const float bx = __shfl_sync(0xFFFFFFFFu, a.x, (v + 1) & 31);
        const float by = __shfl_sync(0xFFFFFFFFu, a.y, (v + 1) & 31);
        const float abx = bx - a.x;
        const float aby = by - a.y;
        s_e0[w][v] = make_float4(a.x, a.y, abx, aby);
        s_e1[w][v] = make_float4(__fdividef(1.0f, abx * abx + aby * aby + EPSF),
                                 __fdividef(1.0f, aby + EPSF),
                                 by, 0.0f);
        __syncwarp();            // order STS before LDS, within this warp only
    }

    // Split accumulators: halves the serial FMNMX dependency chain.
    float mdd0 = 3.402823466e+38f;
    float mdd1 = 3.402823466e+38f;
    int cr0 = 0, cr1 = 0;

#pragma unroll
    for (int e = 0; e < VN; e += 2) {
#pragma unroll
        for (int k = 0; k < 2; ++k) {
            const float4 e0 = s_e0[w][e + k];   // ax, ay, abx, aby (broadcast LDS.128)
            const float4 e1 = s_e1[w][e + k];   // inv2, invdy, by
            const float apx = px - e0.x;
            const float apy = py - e0.y;

            // Squared segment distance (sqrt deferred below — monotone).
            float tt = (apx * e0.z + apy * e0.w) * e1.x;
            tt = fminf(fmaxf(tt, 0.0f), 1.0f);
            const float dx = apx - tt * e0.z;
            const float dy = apy - tt * e0.w;
            const float dd = dx * dx + dy * dy;

            // Ray-crossing (even-odd) test; apy reused as (py - ay).
            const bool straddles = (e0.y > py) != (e1.z > py);
            const float x_int = e0.x + e0.z * (apy * e1.y);
            const int hit = (straddles && (px < x_int)) ? 1 : 0;

            if (k == 0) { mdd0 = fminf(mdd0, dd); cr0 += hit; }
            else        { mdd1 = fminf(mdd1, dd); cr1 += hit; }
        }
    }

    const float mindd = fminf(mdd0, mdd1);
    const int crossings = cr0 + cr1;

    // Final per-thread candidate: 0.5*sqrt is monotone -> applying before the
    // min is exact. inside -> exact 0 (matches jnp.where); outside ->
    // 0.5*sqrt(max(dd, EPS)) matches the reference elementwise.
    const float cand = ((crossings & 1) != 0)
                           ? 0.0f
                           : 0.5f * sqrtf(fmaxf(mindd, EPSF));

    // Warp min (non-neg floats: bit order == numeric order).
    const unsigned uv = __reduce_min_sync(0xFFFFFFFFu, __float_as_uint(cand));

    // PDL ordering: pl_init's +inf store is long done -> instant fast-path.
    cudaGridDependencySynchronize();

    if (v == 0)
        atomicMin(out_bits, uv);   // 256 same-address RED ops ~0.854 cyc/op
}

extern "C" void kernel_launch(void* const* d_in, const int* in_sizes, int n_in,
                              void* d_out, int out_size) {
    const float* last_point     = (const float*)d_in[0];  // [64, 64, 2] f32
    const float* polygon_coords = (const float*)d_in[1];  // [64, 128, 32, 2] f32
    unsigned* out_bits = (unsigned*)d_out;                // scalar f32 output

    pl_init<<<1, 1>>>(out_bits);

    // Producer launched with Programmatic Stream Serialization: its ramp and
    // compute overlap pl_init; ordering enforced on-device just before the
    // atomics via cudaGridDependencySynchronize().
    cudaLaunchConfig_t cfg = {};
    cfg.gridDim  = dim3(PN, 1, 1);
    cfg.blockDim = dim3(MN, 1, 1);
    cfg.dynamicSmemBytes = 0;
    cfg.stream = 0;

    cudaLaunchAttribute attrs[1];
    attrs[0].id = cudaLaunchAttributeProgrammaticStreamSerialization;
    attrs[0].val.programmaticStreamSerializationAllowed = 1;
    cfg.attrs = attrs;
    cfg.numAttrs = 1;

    cudaLaunchKernelEx(&cfg, pl_main, last_point, polygon_coords, out_bits);
}

// round 11
// speedup vs baseline: 1.0435x; 1.0435x over previous
#include <cuda_runtime.h>

// Problem shape (fixed by reference): B=64, M=64, P=128, V=32.
// Output = 0.5 * min over (m,p) of point-polygon distance, BATCH 63 ONLY.
#define BN 64
#define MN 64
#define PN 128
#define VN 32
#define EPSF 1e-12f

#define POLYS_PER_CTA 4
#define NCTA (PN / POLYS_PER_CTA)          // 32 CTAs
#define NTHR (POLYS_PER_CTA * MN)          // 256 threads

// ── Kernel 1: seed d_out with +inf bits (overwrites the 0xAA poison).
__global__ void pl_init(unsigned* __restrict__ out_bits) {
    out_bits[0] = 0x7F800000u;   // +inf
}

// ── Kernel 2 (PDL): full compute; atomicMin of final scalar candidates
//    straight into d_out. Nothing runs after this kernel.
__global__ void __launch_bounds__(NTHR)
pl_main(const float* __restrict__ last_point,
        const float* __restrict__ polygon_coords,
        unsigned* __restrict__ out_bits) {
    // Edge tables for this CTA's 4 polygons.
    // [poly][v]: e0 = { ax, ay, abx, aby }, e1 = { inv2, invdy, by, - }
    __shared__ float4 s_e0[POLYS_PER_CTA][VN];
    __shared__ float4 s_e1[POLYS_PER_CTA][VN];

    const int t  = threadIdx.x;
    const int sp = t >> 6;        // sub-polygon 0..3 (warp-uniform)
    const int m  = t & (MN - 1);  // point index 0..63
    const int p  = blockIdx.x * POLYS_PER_CTA + sp;   // global polygon id

    // This thread's query point: last_point[63, m, :] (hoisted over table build).
    const float2 pt = reinterpret_cast<const float2*>(last_point)[(BN - 1) * MN + m];
    const float px = pt.x;
    const float py = pt.y;

    // Build edge tables: threads 0..127 each own one (poly, edge). Each builder
    // warp loads one polygon's 32 float2 vertices (256B, coalesced).
    if (t < POLYS_PER_CTA * VN) {
        const int bp = t >> 5;          // builder polygon 0..3
        const int v  = t & (VN - 1);    // edge index
        const float2* pc = reinterpret_cast<const float2*>(polygon_coords)
                           + (((BN - 1) * PN + blockIdx.x * POLYS_PER_CTA + bp) * VN);
        const float2 a = pc[v];
        const float2 b = pc[(v + 1) & (VN - 1)];   // roll(-1) over vertex axis
        const float abx = b.x - a.x;
        const float aby = b.y - a.y;
        s_e0[bp][v] = make_float4(a.x, a.y, abx, aby);
        s_e1[bp][v] = make_float4(__fdividef(1.0f, abx * abx + aby * aby + EPSF),
                                  __fdividef(1.0f, aby + EPSF),
                                  b.y, 0.0f);
    }
    __syncthreads();

    float mindd = 3.402823466e+38f;
    int crossings = 0;

#pragma unroll
    for (int v = 0; v < VN; ++v) {
        const float4 e0 = s_e0[sp][v];   // ax, ay, abx, aby (uniform broadcast)
        const float4 e1 = s_e1[sp][v];   // inv2, invdy, by
        const float apx = px - e0.x;
        const float apy = py - e0.y;

        // Squared segment distance (sqrt deferred below — monotone).
        float tt = (apx * e0.z + apy * e0.w) * e1.x;
        tt = fminf(fmaxf(tt, 0.0f), 1.0f);
        const float dx = apx - tt * e0.z;
        const float dy = apy - tt * e0.w;
        mindd = fminf(mindd, dx * dx + dy * dy);

        // Ray-crossing (even-odd) test; apy reused as (py - ay).
        const bool straddles = (e0.y > py) != (e1.z > py);
        const float x_int = e0.x + e0.z * (apy * e1.y);
        if (straddles && (px < x_int)) ++crossings;
    }

    // Final per-thread candidate: 0.5*sqrt is monotone -> applying before the
    // min is exact. inside -> exact 0 (matches jnp.where); outside ->
    // 0.5*sqrt(max(dd, EPS)) matches the reference elementwise.
    const float cand = ((crossings & 1) != 0)
                           ? 0.0f
                           : 0.5f * sqrtf(fmaxf(mindd, EPSF));

    // Warp min (non-neg floats: bit order == numeric order).
    const unsigned uv = __reduce_min_sync(0xFFFFFFFFu, __float_as_uint(cand));

    // PDL ordering: pl_init's +inf store is long done -> instant fast-path.
    cudaGridDependencySynchronize();

    if ((t & 31) == 0)
        atomicMin(out_bits, uv);   // 256 same-address RED ops total ~0.854 cyc/op
}

extern "C" void kernel_launch(void* const* d_in, const int* in_sizes, int n_in,
                              void* d_out, int out_size) {
    const float* last_point     = (const float*)d_in[0];  // [64, 64, 2] f32
    const float* polygon_coords = (const float*)d_in[1];  // [64, 128, 32, 2] f32
    unsigned* out_bits = (unsigned*)d_out;                // scalar f32 output

    pl_init<<<1, 1>>>(out_bits);

    // Producer launched with Programmatic Stream Serialization: its ramp and
    // compute overlap pl_init; ordering enforced on-device just before the
    // atomics via cudaGridDependencySynchronize().
    cudaLaunchConfig_t cfg = {};
    cfg.gridDim  = dim3(NCTA, 1, 1);
    cfg.blockDim = dim3(NTHR, 1, 1);
    cfg.dynamicSmemBytes = 0;
    cfg.stream = 0;

    cudaLaunchAttribute attrs[1];
    attrs[0].id = cudaLaunchAttributeProgrammaticStreamSerialization;
    attrs[0].val.programmaticStreamSerializationAllowed = 1;
    cfg.attrs = attrs;
    cfg.numAttrs = 1;

    cudaLaunchKernelEx(&cfg, pl_main, last_point, polygon_coords, out_bits);
}